// round 15
// baseline (speedup 1.0000x reference)
#include <cuda_runtime.h>
#include <cuda_fp16.h>
#include <math.h>
#include <cstdint>

// Problem constants
#define B_    4
#define H_    128
#define W_    128
#define C_    256
#define NH_   8
#define HD_   32
#define HW_   (H_ * W_)                 // 16384
#define NWIN  (B_ * H_)                 // 512
#define NCTA  (NWIN * NH_)              // 4096
#define QKV_STRIDE ((size_t)B_ * HW_ * C_)

// Scratch: ungated attention output y in fp16 (33.5 MB)
__device__ __align__(16) __half g_yh[(size_t)B_ * HW_ * C_];
__device__ float g_wsum[NWIN];
__device__ float g_M[NWIN];

// ---------------- fp16 m16n8k16 mma.sync (sm_80+ baseline) ----------------
#define MMA_F16(c0, c1, c2, c3, a0, a1, a2, a3, b0, b1) \
    asm volatile("mma.sync.aligned.m16n8k16.row.col.f32.f16.f16.f32 " \
        "{%0,%1,%2,%3}, {%4,%5,%6,%7}, {%8,%9}, {%0,%1,%2,%3};" \
        : "+f"(c0), "+f"(c1), "+f"(c2), "+f"(c3) \
        : "r"(a0), "r"(a1), "r"(a2), "r"(a3), "r"(b0), "r"(b1))

#define LDSM_X4(r0, r1, r2, r3, addr) \
    asm volatile("ldmatrix.sync.aligned.m8n8.x4.shared.b16 {%0,%1,%2,%3}, [%4];" \
        : "=r"(r0), "=r"(r1), "=r"(r2), "=r"(r3) : "r"(addr))

#define LDSM_X4T(r0, r1, r2, r3, addr) \
    asm volatile("ldmatrix.sync.aligned.m8n8.x4.trans.shared.b16 {%0,%1,%2,%3}, [%4];" \
        : "=r"(r0), "=r"(r1), "=r"(r2), "=r"(r3) : "r"(addr))

__device__ __forceinline__ uint32_t h2u(__half2 h) { return *(uint32_t*)&h; }
__device__ __forceinline__ uint32_t smem_u32(const void* p) {
    uint32_t a;
    asm("{ .reg .u64 t; cvta.to.shared.u64 t, %1; cvt.u32.u64 %0, t; }"
        : "=r"(a) : "l"(p));
    return a;
}

// ---------------- fused kernel smem layout (u32 word offsets) --------------
// QHP/KHP/VHP: [128 rows][20 stride] fp16x2 d-pairs (single plane each)
// SCT: float2[128] sincos; SQ: [2][128] row-sumsq halves
// OX (aliases QHP+KHP, dead after the full barrier): [8 pairs][32 lanes][16 f32]
#define QHP_U      0
#define KHP_U      2560
#define VHP_U      5120
#define SCT_U      7680
#define SQ_U       7936
#define OX_U       0
#define SMEM_WORDS 8192
#define FUSED_SMEM (SMEM_WORDS * 4)    // 32,768 bytes

#define A127 (3.14159265358979323846f / 127.0f)

// ---------------------------------------------------------------------------
// Fused kernel, per (window, head), 512 threads / 16 warps:
//   warp (wp = wid>>1, hf = wid&1) owns rows 16wp..+15 x cols 64hf..+63.
//   1. stage Q/K/V single-plane fp16 (uniform [token][20] layout)
//   2. mma accumulators pre-loaded with the RPE bias; QK^T over the col half
//   3. |.| sums via per-warp atomicAdd; row sumsq exchanged between the two
//      col-half warps through smem + ONE full barrier (doubles as fence that
//      frees Q/K staging for the oacc-exchange buffer)
//   4. 1-cos packed to half2 A-frags; AV over the warp's k half
//   5. odd warp writes partial oacc to smem, pair bar.sync(64); even warp
//      adds both halves and stores y (fp16, ungated)
// ---------------------------------------------------------------------------
__global__ __launch_bounds__(512, 2) void fused_kernel(const float* __restrict__ qkv) {
    extern __shared__ uint32_t smu[];
    float* smf = (float*)smu;

    const int bx  = blockIdx.x;        // 0..4095
    const int wi  = bx >> 3;
    const int n   = bx & 7;
    const int b   = wi >> 7;
    const int h   = wi & 127;
    const int tid = threadIdx.x;
    const int wid = tid >> 5;
    const int lane = tid & 31;
    const int wp  = wid >> 1;          // row strip 0..7
    const int hf  = wid & 1;           // col half 0/1

    // sincos table for the RPE bias identity
    if (tid < 128) {
        float a = (float)tid * A127;
        smf[SCT_U + 2 * tid]     = sinf(a);
        smf[SCT_U + 2 * tid + 1] = cosf(a);
    }

    const float* qb = qkv + ((size_t)(b * HW_) + (size_t)h * W_) * C_ + n * HD_;
    const float* kb = qb + QKV_STRIDE;
    const float* vb = kb + QKV_STRIDE;

    // Stage Q/K/V (single fp16 plane each): packed d-pairs, row stride 20
    #pragma unroll
    for (int t = 0; t < 2; ++t) {
        int idx = tid + t * 512;       // 1024 float4 chunks
        int w   = idx >> 3;            // row 0..127
        int d4  = (idx & 7) << 2;      // 0,4,...,28
        float4 qv = *(const float4*)(qb + (size_t)w * C_ + d4);
        float4 kv = *(const float4*)(kb + (size_t)w * C_ + d4);
        float4 vv = *(const float4*)(vb + (size_t)w * C_ + d4);
        int base = w * 20 + (d4 >> 1);
        uint2 qs, ks, vs;
        qs.x = h2u(__floats2half2_rn(qv.x, qv.y));
        qs.y = h2u(__floats2half2_rn(qv.z, qv.w));
        ks.x = h2u(__floats2half2_rn(kv.x, kv.y));
        ks.y = h2u(__floats2half2_rn(kv.z, kv.w));
        vs.x = h2u(__floats2half2_rn(vv.x, vv.y));
        vs.y = h2u(__floats2half2_rn(vv.z, vv.w));
        *(uint2*)(smu + QHP_U + base) = qs;
        *(uint2*)(smu + KHP_U + base) = ks;
        *(uint2*)(smu + VHP_U + base) = vs;
    }
    __syncthreads();

    // ldmatrix per-lane base addresses (bytes)
    const uint32_t smb = smem_u32(smu);
    const uint32_t qrow  = 16 * wp + (lane & 7) + 8 * ((lane >> 3) & 1);
    const uint32_t qaddr = smb + 4 * (QHP_U + qrow * 20 + 4 * ((lane >> 4) & 1));
    const uint32_t krow  = 64 * hf + (lane & 7) + 8 * ((lane >> 4) & 1);
    const uint32_t kaddr = smb + 4 * (KHP_U + krow * 20 + 4 * ((lane >> 3) & 1));
    const uint32_t vrow  = 64 * hf + (lane & 7) + 8 * ((lane >> 3) & 1);
    const uint32_t vaddr = smb + 4 * (VHP_U + vrow * 20 + 4 * ((lane >> 4) & 1));

    const int jl   = lane & 3;
    const int r1 = 16 * wp + (lane >> 2);
    const int r2 = r1 + 8;

    // ---- init accumulators with RPE bias: bias = bs2*sin((col-row)*pi/127)
    const float bs2 = 0.2f * sinf((float)h * (3.14159265358979323846f / 128.0f));
    const float f1c = bs2 * cosf((float)r1 * A127);
    const float f1s = bs2 * sinf((float)r1 * A127);
    const float f2c = bs2 * cosf((float)r2 * A127);
    const float f2s = bs2 * sinf((float)r2 * A127);

    float c[8][4];
    #pragma unroll
    for (int nt = 0; nt < 8; ++nt) {
        const int col0 = 64 * hf + 8 * nt + 2 * jl;
        float4 t = *(const float4*)(smf + SCT_U + 2 * col0);   // {s0,c0,s1,c1}
        c[nt][0] = t.x * f1c - t.y * f1s;
        c[nt][1] = t.z * f1c - t.w * f1s;
        c[nt][2] = t.x * f2c - t.y * f2s;
        c[nt][3] = t.z * f2c - t.w * f2s;
    }

    // ---- QK^T over this warp's 64-col half, 2 chunks of k16 ----
    #pragma unroll
    for (int ch = 0; ch < 2; ++ch) {
        uint32_t qh0, qh1, qh2, qh3;
        LDSM_X4(qh0, qh1, qh2, qh3, qaddr + ch * 32);
        #pragma unroll
        for (int t = 0; t < 4; ++t) {
            uint32_t k00, k01, k10, k11;
            LDSM_X4(k00, k01, k10, k11, kaddr + t * 1280 + ch * 32);  // 16 rows*80B
            MMA_F16(c[2*t][0], c[2*t][1], c[2*t][2], c[2*t][3],
                    qh0, qh1, qh2, qh3, k00, k01);
            MMA_F16(c[2*t+1][0], c[2*t+1][1], c[2*t+1][2], c[2*t+1][3],
                    qh0, qh1, qh2, qh3, k10, k11);
        }
    }

    // ---- |.| sums + partial row sumsq over this half ----
    float sq1 = 0.0f, sq2 = 0.0f, s_abs = 0.0f;
    #pragma unroll
    for (int nt = 0; nt < 8; ++nt) {
        sq1 += c[nt][0] * c[nt][0] + c[nt][1] * c[nt][1];
        sq2 += c[nt][2] * c[nt][2] + c[nt][3] * c[nt][3];
        s_abs += fabsf(c[nt][0]) + fabsf(c[nt][1]) + fabsf(c[nt][2]) + fabsf(c[nt][3]);
    }
    sq1 += __shfl_xor_sync(0xffffffffu, sq1, 1);
    sq1 += __shfl_xor_sync(0xffffffffu, sq1, 2);
    sq2 += __shfl_xor_sync(0xffffffffu, sq2, 1);
    sq2 += __shfl_xor_sync(0xffffffffu, sq2, 2);
    #pragma unroll
    for (int m = 16; m; m >>= 1)
        s_abs += __shfl_xor_sync(0xffffffffu, s_abs, m);
    if (lane == 0) atomicAdd(&g_wsum[wi], s_abs);

    // ---- exchange row sumsq halves (full barrier: also frees Q/K region) ----
    if (jl == 0) {
        smf[SQ_U + hf * 128 + r1] = sq1;
        smf[SQ_U + hf * 128 + r2] = sq2;
    }
    __syncthreads();   // after this: all Q/K LDSM reads complete -> OX may alias
    sq1 += smf[SQ_U + (1 - hf) * 128 + r1];
    sq2 += smf[SQ_U + (1 - hf) * 128 + r2];

    // ---- transform: pack 1-cos(v*(pi/2)/norm) straight to half2 A-frags ----
    uint32_t aw[8][2];
    {
        const float inv1 = 1.57079632679489662f / fmaxf(sqrtf(sq1), 1e-12f);
        const float inv2 = 1.57079632679489662f / fmaxf(sqrtf(sq2), 1e-12f);
        #pragma unroll
        for (int nt = 0; nt < 8; ++nt) {
            float t0 = 1.0f - __cosf(c[nt][0] * inv1);
            float t1 = 1.0f - __cosf(c[nt][1] * inv1);
            float t2 = 1.0f - __cosf(c[nt][2] * inv2);
            float t3 = 1.0f - __cosf(c[nt][3] * inv2);
            aw[nt][0] = h2u(__floats2half2_rn(t0, t1));
            aw[nt][1] = h2u(__floats2half2_rn(t2, t3));
        }
    }

    // ---- AV over this warp's 64-k half: partial 16x32 ----
    float oacc[4][4];
    #pragma unroll
    for (int nt = 0; nt < 4; ++nt)
        #pragma unroll
        for (int j = 0; j < 4; ++j) oacc[nt][j] = 0.0f;

    #pragma unroll
    for (int ch = 0; ch < 4; ++ch) {
        const uint32_t ah0 = aw[2 * ch][0];
        const uint32_t ah1 = aw[2 * ch][1];
        const uint32_t ah2 = aw[2 * ch + 1][0];
        const uint32_t ah3 = aw[2 * ch + 1][1];

        uint32_t v00, v01, v02, v03, v10, v11, v12, v13;
        LDSM_X4T(v00, v01, v02, v03, vaddr + ch * 1280);        // d 0-15
        LDSM_X4T(v10, v11, v12, v13, vaddr + ch * 1280 + 32);   // d 16-31
        MMA_F16(oacc[0][0], oacc[0][1], oacc[0][2], oacc[0][3],
                ah0, ah1, ah2, ah3, v00, v01);
        MMA_F16(oacc[1][0], oacc[1][1], oacc[1][2], oacc[1][3],
                ah0, ah1, ah2, ah3, v02, v03);
        MMA_F16(oacc[2][0], oacc[2][1], oacc[2][2], oacc[2][3],
                ah0, ah1, ah2, ah3, v10, v11);
        MMA_F16(oacc[3][0], oacc[3][1], oacc[3][2], oacc[3][3],
                ah0, ah1, ah2, ah3, v12, v13);
    }

    // ---- pair reduction: odd half writes partial, even half adds + stores ----
    float* ox = smf + OX_U + (wp * 32 + lane) * 16;
    if (hf) {
        #pragma unroll
        for (int nt = 0; nt < 4; ++nt)
            *(float4*)(ox + 4 * nt) = *(float4*)(oacc[nt]);
    }
    asm volatile("bar.sync %0, 64;" :: "r"(wp + 1) : "memory");
    if (!hf) {
        const size_t obase = ((size_t)(b * HW_) + (size_t)h * W_) * C_ + n * HD_;
        const int ocol = 2 * jl;
        #pragma unroll
        for (int nt = 0; nt < 4; ++nt) {
            float4 p = *(const float4*)(ox + 4 * nt);
            __half2 p1 = __floats2half2_rn(oacc[nt][0] + p.x, oacc[nt][1] + p.y);
            __half2 p2 = __floats2half2_rn(oacc[nt][2] + p.z, oacc[nt][3] + p.w);
            *(__half2*)(g_yh + obase + (size_t)r1 * C_ + 8 * nt + ocol) = p1;
            *(__half2*)(g_yh + obase + (size_t)r2 * C_ + 8 * nt + ocol) = p2;
        }
    }
}

// ---------------------------------------------------------------------------
// Gate: mean |attn| per window, global max, M = max(mean/max, 0.5).
// Resets g_wsum for the next graph replay.
// ---------------------------------------------------------------------------
__global__ void gate_kernel() {
    __shared__ float red[512];
    const int t = threadIdx.x;
    float mean = g_wsum[t] * (1.0f / 131072.0f);   // / (NH*W*W)
    g_wsum[t] = 0.0f;
    red[t] = mean;
    __syncthreads();
    for (int s = 256; s > 0; s >>= 1) {
        if (t < s) red[t] = fmaxf(red[t], red[t + s]);
        __syncthreads();
    }
    g_M[t] = fmaxf(mean / red[0], 0.5f);
}

// ---------------------------------------------------------------------------
// Blend: out = M * y + (1 - M) * res   (pure bandwidth)
// ---------------------------------------------------------------------------
__global__ __launch_bounds__(256) void blend_kernel(const float* __restrict__ resx,
                                                    float* __restrict__ out) {
    const int i  = blockIdx.x * 256 + threadIdx.x;   // float4 index
    const int wi = i >> 13;                          // / (W_*C_/4 = 8192)
    const float Mw   = g_M[wi];
    const float oneM = 1.0f - Mw;
    const __half2* yp = (const __half2*)g_yh + 2 * (size_t)i;
    float2 y01 = __half22float2(yp[0]);
    float2 y23 = __half22float2(yp[1]);
    float4 r = ((const float4*)resx)[i];
    float4 o;
    o.x = fmaf(Mw, y01.x, oneM * r.x);
    o.y = fmaf(Mw, y01.y, oneM * r.y);
    o.z = fmaf(Mw, y23.x, oneM * r.z);
    o.w = fmaf(Mw, y23.y, oneM * r.w);
    ((float4*)out)[i] = o;
}

// ---------------------------------------------------------------------------
extern "C" void kernel_launch(void* const* d_in, const int* in_sizes, int n_in,
                              void* d_out, int out_size) {
    (void)in_sizes; (void)n_in; (void)out_size;
    const float* qkv  = (const float*)d_in[0];
    const float* resx = (const float*)d_in[1];
    float* out = (float*)d_out;

    cudaFuncSetAttribute(fused_kernel, cudaFuncAttributeMaxDynamicSharedMemorySize,
                         FUSED_SMEM);

    fused_kernel<<<NCTA, 512, FUSED_SMEM>>>(qkv);
    gate_kernel<<<1, NWIN>>>();
    blend_kernel<<<(B_ * HW_ * C_ / 4) / 256, 256>>>(resx, out);
}

// round 16
// speedup vs baseline: 1.3451x; 1.3451x over previous
#include <cuda_runtime.h>
#include <cuda_fp16.h>
#include <math.h>
#include <cstdint>

// Problem constants
#define B_    4
#define H_    128
#define W_    128
#define C_    256
#define NH_   8
#define HD_   32
#define HW_   (H_ * W_)                 // 16384
#define NWIN  (B_ * H_)                 // 512
#define NCTA  (NWIN * NH_)              // 4096
#define QKV_STRIDE ((size_t)B_ * HW_ * C_)

// Scratch: ungated attention output y in fp16 (33.5 MB)
__device__ __align__(16) __half g_yh[(size_t)B_ * HW_ * C_];
__device__ float g_wsum[NWIN];
__device__ float g_M[NWIN];

// ---------------- fp16 m16n8k16 mma.sync (sm_80+ baseline) ----------------
#define MMA_F16(c0, c1, c2, c3, a0, a1, a2, a3, b0, b1) \
    asm volatile("mma.sync.aligned.m16n8k16.row.col.f32.f16.f16.f32 " \
        "{%0,%1,%2,%3}, {%4,%5,%6,%7}, {%8,%9}, {%0,%1,%2,%3};" \
        : "+f"(c0), "+f"(c1), "+f"(c2), "+f"(c3) \
        : "r"(a0), "r"(a1), "r"(a2), "r"(a3), "r"(b0), "r"(b1))

#define LDSM_X4(r0, r1, r2, r3, addr) \
    asm volatile("ldmatrix.sync.aligned.m8n8.x4.shared.b16 {%0,%1,%2,%3}, [%4];" \
        : "=r"(r0), "=r"(r1), "=r"(r2), "=r"(r3) : "r"(addr))

#define LDSM_X4T(r0, r1, r2, r3, addr) \
    asm volatile("ldmatrix.sync.aligned.m8n8.x4.trans.shared.b16 {%0,%1,%2,%3}, [%4];" \
        : "=r"(r0), "=r"(r1), "=r"(r2), "=r"(r3) : "r"(addr))

// streaming store of a half2 pair (no L2 persistence)
#define STG32_CS(ptr, v) \
    asm volatile("st.global.cs.b32 [%0], %1;" :: "l"(ptr), "r"(v) : "memory")

__device__ __forceinline__ uint32_t h2u(__half2 h) { return *(uint32_t*)&h; }
__device__ __forceinline__ uint32_t smem_u32(const void* p) {
    uint32_t a;
    asm("{ .reg .u64 t; cvta.to.shared.u64 t, %1; cvt.u32.u64 %0, t; }"
        : "=r"(a) : "l"(p));
    return a;
}

// ---------------- fused kernel smem layout (u32 word offsets) --------------
// QHP/KHP/VHP: [128 rows][20 stride] fp16x2 d-pairs (single plane each)
// SCT: float2[128] {sin(k*pi/127), cos(k*pi/127)}
#define QHP_U      0
#define KHP_U      2560
#define VHP_U      5120
#define SCT_U      7680
#define SMEM_WORDS 7936
#define FUSED_SMEM (SMEM_WORDS * 4)    // 31,744 bytes

#define A127 (3.14159265358979323846f / 127.0f)

// ---------------------------------------------------------------------------
// Fused kernel, per (window, head):
//   1. stage Q/K/V single-plane fp16 in smem, uniform [token][20] layout
//   2. init mma accumulators with the RPE bias (2*sin((k-q)pi/127) identity)
//   3. QK^T: 1 mma per k16 tile (bias pre-added via accumulator init)
//   4. |.| sums via per-warp atomicAdd (no smem staging, no extra barrier),
//      per-row L2 norm via rsqrt (intra-warp), 1-cos packed to half2 A-frags
//   5. AV: V B-fragments via ldmatrix.x4.trans; y stored fp16 streaming (.cs)
// Exactly ONE __syncthreads (after staging).
// ---------------------------------------------------------------------------
__global__ __launch_bounds__(256, 3) void fused_kernel(const float* __restrict__ qkv) {
    extern __shared__ uint32_t smu[];
    float* smf = (float*)smu;

    const int bx  = blockIdx.x;        // 0..4095
    const int wi  = bx >> 3;
    const int n   = bx & 7;
    const int b   = wi >> 7;
    const int h   = wi & 127;
    const int tid = threadIdx.x;
    const int wid = tid >> 5;
    const int lane = tid & 31;

    // sincos table for the RPE bias identity
    if (tid < 128) {
        float a = (float)tid * A127;
        smf[SCT_U + 2 * tid]     = sinf(a);
        smf[SCT_U + 2 * tid + 1] = cosf(a);
    }

    const float* qb = qkv + ((size_t)(b * HW_) + (size_t)h * W_) * C_ + n * HD_;
    const float* kb = qb + QKV_STRIDE;
    const float* vb = kb + QKV_STRIDE;

    // Stage Q/K/V (single fp16 plane each): packed d-pairs, row stride 20
    #pragma unroll
    for (int t = 0; t < 4; ++t) {
        int idx = tid + t * 256;       // 1024 float4 chunks
        int w   = idx >> 3;            // row 0..127
        int d4  = (idx & 7) << 2;      // 0,4,...,28
        float4 qv = *(const float4*)(qb + (size_t)w * C_ + d4);
        float4 kv = *(const float4*)(kb + (size_t)w * C_ + d4);
        float4 vv = *(const float4*)(vb + (size_t)w * C_ + d4);
        int base = w * 20 + (d4 >> 1);
        uint2 qs, ks, vs;
        qs.x = h2u(__floats2half2_rn(qv.x, qv.y));
        qs.y = h2u(__floats2half2_rn(qv.z, qv.w));
        ks.x = h2u(__floats2half2_rn(kv.x, kv.y));
        ks.y = h2u(__floats2half2_rn(kv.z, kv.w));
        vs.x = h2u(__floats2half2_rn(vv.x, vv.y));
        vs.y = h2u(__floats2half2_rn(vv.z, vv.w));
        *(uint2*)(smu + QHP_U + base) = qs;
        *(uint2*)(smu + KHP_U + base) = ks;
        *(uint2*)(smu + VHP_U + base) = vs;
    }
    __syncthreads();

    // ldmatrix per-lane base addresses (bytes)
    const uint32_t smb = smem_u32(smu);
    const uint32_t qrow  = 16 * wid + (lane & 7) + 8 * ((lane >> 3) & 1);
    const uint32_t qaddr = smb + 4 * (QHP_U + qrow * 20 + 4 * ((lane >> 4) & 1));
    const uint32_t krow  = (lane & 7) + 8 * ((lane >> 4) & 1);
    const uint32_t kaddr = smb + 4 * (KHP_U + krow * 20 + 4 * ((lane >> 3) & 1));
    const uint32_t vrow  = (lane & 7) + 8 * ((lane >> 3) & 1);
    const uint32_t vaddr = smb + 4 * (VHP_U + vrow * 20 + 4 * ((lane >> 4) & 1));

    const int arow = 16 * wid + (lane >> 2);
    const int jl   = lane & 3;
    const int r1 = arow;
    const int r2 = arow + 8;

    // ---- init accumulators with RPE bias: bias = bs2*sin((col-row)*pi/127)
    const float bs2 = 0.2f * sinf((float)h * (3.14159265358979323846f / 128.0f));
    const float f1c = bs2 * cosf((float)r1 * A127);
    const float f1s = bs2 * sinf((float)r1 * A127);
    const float f2c = bs2 * cosf((float)r2 * A127);
    const float f2s = bs2 * sinf((float)r2 * A127);

    float c[16][4];
    #pragma unroll
    for (int nt = 0; nt < 16; ++nt) {
        const int col0 = 8 * nt + 2 * jl;
        float4 t = *(const float4*)(smf + SCT_U + 2 * col0);   // {s0,c0,s1,c1}
        c[nt][0] = t.x * f1c - t.y * f1s;
        c[nt][1] = t.z * f1c - t.w * f1s;
        c[nt][2] = t.x * f2c - t.y * f2s;
        c[nt][3] = t.z * f2c - t.w * f2s;
    }

    // ---- QK^T: warp wid -> rows 16*wid..16*wid+15, 2 chunks of k16 ----
    #pragma unroll
    for (int ch = 0; ch < 2; ++ch) {
        uint32_t qh0, qh1, qh2, qh3;
        LDSM_X4(qh0, qh1, qh2, qh3, qaddr + ch * 32);
        #pragma unroll
        for (int t = 0; t < 8; ++t) {
            uint32_t k00, k01, k10, k11;
            LDSM_X4(k00, k01, k10, k11, kaddr + t * 1280 + ch * 32);  // 16 rows * 80B
            MMA_F16(c[2*t][0], c[2*t][1], c[2*t][2], c[2*t][3],
                    qh0, qh1, qh2, qh3, k00, k01);
            MMA_F16(c[2*t+1][0], c[2*t+1][1], c[2*t+1][2], c[2*t+1][3],
                    qh0, qh1, qh2, qh3, k10, k11);
        }
    }

    // ---- epilogue: |.| sums + row sumsq (bias already inside c) ----
    float sq1 = 0.0f, sq2 = 0.0f, s_abs = 0.0f;
    #pragma unroll
    for (int nt = 0; nt < 16; ++nt) {
        sq1 += c[nt][0] * c[nt][0] + c[nt][1] * c[nt][1];
        sq2 += c[nt][2] * c[nt][2] + c[nt][3] * c[nt][3];
        s_abs += fabsf(c[nt][0]) + fabsf(c[nt][1]) + fabsf(c[nt][2]) + fabsf(c[nt][3]);
    }
    sq1 += __shfl_xor_sync(0xffffffffu, sq1, 1);
    sq1 += __shfl_xor_sync(0xffffffffu, sq1, 2);
    sq2 += __shfl_xor_sync(0xffffffffu, sq2, 1);
    sq2 += __shfl_xor_sync(0xffffffffu, sq2, 2);
    #pragma unroll
    for (int m = 16; m; m >>= 1)
        s_abs += __shfl_xor_sync(0xffffffffu, s_abs, m);
    if (lane == 0) atomicAdd(&g_wsum[wi], s_abs);   // per-warp, no smem/barrier

    // ---- transform: pack 1-cos(v*(pi/2)/norm) straight to half2 A-frags ----
    uint32_t aw[16][2];
    {
        const float inv1 = 1.57079632679489662f * rsqrtf(fmaxf(sq1, 1e-24f));
        const float inv2 = 1.57079632679489662f * rsqrtf(fmaxf(sq2, 1e-24f));
        #pragma unroll
        for (int nt = 0; nt < 16; ++nt) {
            float t0 = 1.0f - __cosf(c[nt][0] * inv1);
            float t1 = 1.0f - __cosf(c[nt][1] * inv1);
            float t2 = 1.0f - __cosf(c[nt][2] * inv2);
            float t3 = 1.0f - __cosf(c[nt][3] * inv2);
            aw[nt][0] = h2u(__floats2half2_rn(t0, t1));
            aw[nt][1] = h2u(__floats2half2_rn(t2, t3));
        }
    }

    // ---- AV: A-frags from aw, V B-frags via ldmatrix.trans ----
    float oacc[4][4];
    #pragma unroll
    for (int nt = 0; nt < 4; ++nt)
        #pragma unroll
        for (int j = 0; j < 4; ++j) oacc[nt][j] = 0.0f;

    #pragma unroll
    for (int ch = 0; ch < 8; ++ch) {
        const uint32_t ah0 = aw[2 * ch][0];
        const uint32_t ah1 = aw[2 * ch][1];
        const uint32_t ah2 = aw[2 * ch + 1][0];
        const uint32_t ah3 = aw[2 * ch + 1][1];

        uint32_t v00, v01, v02, v03, v10, v11, v12, v13;
        LDSM_X4T(v00, v01, v02, v03, vaddr + ch * 1280);        // d 0-15
        LDSM_X4T(v10, v11, v12, v13, vaddr + ch * 1280 + 32);   // d 16-31
        MMA_F16(oacc[0][0], oacc[0][1], oacc[0][2], oacc[0][3],
                ah0, ah1, ah2, ah3, v00, v01);
        MMA_F16(oacc[1][0], oacc[1][1], oacc[1][2], oacc[1][3],
                ah0, ah1, ah2, ah3, v02, v03);
        MMA_F16(oacc[2][0], oacc[2][1], oacc[2][2], oacc[2][3],
                ah0, ah1, ah2, ah3, v10, v11);
        MMA_F16(oacc[3][0], oacc[3][1], oacc[3][2], oacc[3][3],
                ah0, ah1, ah2, ah3, v12, v13);
    }

    // ---- store y (ungated) as fp16 with streaming hint ----
    const size_t obase = ((size_t)(b * HW_) + (size_t)h * W_) * C_ + n * HD_;
    const int ocol = 2 * jl;
    #pragma unroll
    for (int nt = 0; nt < 4; ++nt) {
        uint32_t p1 = h2u(__floats2half2_rn(oacc[nt][0], oacc[nt][1]));
        uint32_t p2 = h2u(__floats2half2_rn(oacc[nt][2], oacc[nt][3]));
        STG32_CS(g_yh + obase + (size_t)r1 * C_ + 8 * nt + ocol, p1);
        STG32_CS(g_yh + obase + (size_t)r2 * C_ + 8 * nt + ocol, p2);
    }
}

// ---------------------------------------------------------------------------
// Gate: mean |attn| per window, global max, M = max(mean/max, 0.5).
// Resets g_wsum for the next graph replay.
// ---------------------------------------------------------------------------
__global__ void gate_kernel() {
    __shared__ float red[512];
    const int t = threadIdx.x;
    float mean = g_wsum[t] * (1.0f / 131072.0f);   // / (NH*W*W)
    g_wsum[t] = 0.0f;
    red[t] = mean;
    __syncthreads();
    for (int s = 256; s > 0; s >>= 1) {
        if (t < s) red[t] = fmaxf(red[t], red[t + s]);
        __syncthreads();
    }
    g_M[t] = fmaxf(mean / red[0], 0.5f);
}

// ---------------------------------------------------------------------------
// Blend: out = M * y + (1 - M) * res   (pure bandwidth, streaming hints)
// ---------------------------------------------------------------------------
__global__ __launch_bounds__(256) void blend_kernel(const float* __restrict__ resx,
                                                    float* __restrict__ out) {
    const int i  = blockIdx.x * 256 + threadIdx.x;   // float4 index
    const int wi = i >> 13;                          // / (W_*C_/4 = 8192)
    const float Mw   = g_M[wi];
    const float oneM = 1.0f - Mw;
    uint2 yr;
    asm volatile("ld.global.cs.v2.b32 {%0,%1}, [%2];"
                 : "=r"(yr.x), "=r"(yr.y)
                 : "l"((const __half2*)g_yh + 2 * (size_t)i));
    float2 y01 = __half22float2(*(__half2*)&yr.x);
    float2 y23 = __half22float2(*(__half2*)&yr.y);
    float4 r;
    asm volatile("ld.global.cs.v4.f32 {%0,%1,%2,%3}, [%4];"
                 : "=f"(r.x), "=f"(r.y), "=f"(r.z), "=f"(r.w)
                 : "l"(resx + 4 * (size_t)i));
    float4 o;
    o.x = fmaf(Mw, y01.x, oneM * r.x);
    o.y = fmaf(Mw, y01.y, oneM * r.y);
    o.z = fmaf(Mw, y23.x, oneM * r.z);
    o.w = fmaf(Mw, y23.y, oneM * r.w);
    asm volatile("st.global.cs.v4.f32 [%0], {%1,%2,%3,%4};"
                 :: "l"(out + 4 * (size_t)i),
                    "f"(o.x), "f"(o.y), "f"(o.z), "f"(o.w) : "memory");
}

// ---------------------------------------------------------------------------
extern "C" void kernel_launch(void* const* d_in, const int* in_sizes, int n_in,
                              void* d_out, int out_size) {
    (void)in_sizes; (void)n_in; (void)out_size;
    const float* qkv  = (const float*)d_in[0];
    const float* resx = (const float*)d_in[1];
    float* out = (float*)d_out;

    cudaFuncSetAttribute(fused_kernel, cudaFuncAttributeMaxDynamicSharedMemorySize,
                         FUSED_SMEM);

    fused_kernel<<<NCTA, 256, FUSED_SMEM>>>(qkv);
    gate_kernel<<<1, NWIN>>>();
    blend_kernel<<<(B_ * HW_ * C_ / 4) / 256, 256>>>(resx, out);
}

// round 17
// speedup vs baseline: 1.3740x; 1.0215x over previous
#include <cuda_runtime.h>
#include <cuda_fp16.h>
#include <math.h>
#include <cstdint>

// Problem constants
#define B_    4
#define H_    128
#define W_    128
#define C_    256
#define NH_   8
#define HD_   32
#define HW_   (H_ * W_)                 // 16384
#define NWIN  (B_ * H_)                 // 512
#define NCTA  (NWIN * NH_)              // 4096
#define QKV_STRIDE ((size_t)B_ * HW_ * C_)

// Scratch: ungated attention output y in fp16 (33.5 MB)
__device__ __align__(16) __half g_yh[(size_t)B_ * HW_ * C_];
__device__ float g_wsum[NWIN];
__device__ float g_M[NWIN];

// ---------------- fp16 m16n8k16 mma.sync (sm_80+ baseline) ----------------
#define MMA_F16(c0, c1, c2, c3, a0, a1, a2, a3, b0, b1) \
    asm volatile("mma.sync.aligned.m16n8k16.row.col.f32.f16.f16.f32 " \
        "{%0,%1,%2,%3}, {%4,%5,%6,%7}, {%8,%9}, {%0,%1,%2,%3};" \
        : "+f"(c0), "+f"(c1), "+f"(c2), "+f"(c3) \
        : "r"(a0), "r"(a1), "r"(a2), "r"(a3), "r"(b0), "r"(b1))

#define LDSM_X4(r0, r1, r2, r3, addr) \
    asm volatile("ldmatrix.sync.aligned.m8n8.x4.shared.b16 {%0,%1,%2,%3}, [%4];" \
        : "=r"(r0), "=r"(r1), "=r"(r2), "=r"(r3) : "r"(addr))

#define LDSM_X4T(r0, r1, r2, r3, addr) \
    asm volatile("ldmatrix.sync.aligned.m8n8.x4.trans.shared.b16 {%0,%1,%2,%3}, [%4];" \
        : "=r"(r0), "=r"(r1), "=r"(r2), "=r"(r3) : "r"(addr))

// streaming store (no L2 persistence)
#define STG32_CS(ptr, v) \
    asm volatile("st.global.cs.b32 [%0], %1;" :: "l"(ptr), "r"(v) : "memory")

// streaming read-once global float4 load
#define LDG128_NC_CS(v, ptr) \
    asm volatile("ld.global.nc.cs.v4.f32 {%0,%1,%2,%3}, [%4];" \
        : "=f"((v).x), "=f"((v).y), "=f"((v).z), "=f"((v).w) : "l"(ptr))

__device__ __forceinline__ uint32_t h2u(__half2 h) { return *(uint32_t*)&h; }
__device__ __forceinline__ uint32_t smem_u32(const void* p) {
    uint32_t a;
    asm("{ .reg .u64 t; cvta.to.shared.u64 t, %1; cvt.u32.u64 %0, t; }"
        : "=r"(a) : "l"(p));
    return a;
}

// ---------------- fused kernel smem layout (u32 word offsets) --------------
// QHP/KHP/VHP: [128 rows][20 stride] fp16x2 d-pairs (single plane each)
// SCT: float2[128] {sin(k*pi/127), cos(k*pi/127)}
#define QHP_U      0
#define KHP_U      2560
#define VHP_U      5120
#define SCT_U      7680
#define SMEM_WORDS 7936
#define FUSED_SMEM (SMEM_WORDS * 4)    // 31,744 bytes

#define A127 (3.14159265358979323846f / 127.0f)

// ---------------------------------------------------------------------------
// Fused kernel, per (window, head):
//   1. stage Q/K/V single-plane fp16 in smem, uniform [token][20] layout
//   2. init mma accumulators with the RPE bias (2*sin((k-q)pi/127) identity);
//      per-row sin/cos come from the SCT table (no libm sin/cos anywhere)
//   3. QK^T: 1 mma per k16 tile (bias pre-added via accumulator init)
//   4. |.| sums via per-warp atomicAdd, row L2 norm via rsqrt (intra-warp),
//      1-cos packed to half2 A-frags
//   5. AV: V B-fragments via ldmatrix.x4.trans; y stored fp16 streaming (.cs)
// Exactly ONE __syncthreads (after staging).
// ---------------------------------------------------------------------------
__global__ __launch_bounds__(256, 3) void fused_kernel(const float* __restrict__ qkv) {
    extern __shared__ uint32_t smu[];
    float* smf = (float*)smu;

    const int bx  = blockIdx.x;        // 0..4095
    const int wi  = bx >> 3;
    const int n   = bx & 7;
    const int b   = wi >> 7;
    const int h   = wi & 127;
    const int tid = threadIdx.x;
    const int wid = tid >> 5;
    const int lane = tid & 31;

    // sincos table for the RPE bias identity (fast intrinsics: arg in [0,pi],
    // abs err ~1e-6 on a bias of magnitude <=0.2 -- negligible vs logits O(5))
    if (tid < 128) {
        float a = (float)tid * A127;
        smf[SCT_U + 2 * tid]     = __sinf(a);
        smf[SCT_U + 2 * tid + 1] = __cosf(a);
    }

    const float* qb = qkv + ((size_t)(b * HW_) + (size_t)h * W_) * C_ + n * HD_;
    const float* kb = qb + QKV_STRIDE;
    const float* vb = kb + QKV_STRIDE;

    // Stage Q/K/V (single fp16 plane each): packed d-pairs, row stride 20
    #pragma unroll
    for (int t = 0; t < 4; ++t) {
        int idx = tid + t * 256;       // 1024 float4 chunks
        int w   = idx >> 3;            // row 0..127
        int d4  = (idx & 7) << 2;      // 0,4,...,28
        float4 qv, kv, vv;
        LDG128_NC_CS(qv, qb + (size_t)w * C_ + d4);
        LDG128_NC_CS(kv, kb + (size_t)w * C_ + d4);
        LDG128_NC_CS(vv, vb + (size_t)w * C_ + d4);
        int base = w * 20 + (d4 >> 1);
        uint2 qs, ks, vs;
        qs.x = h2u(__floats2half2_rn(qv.x, qv.y));
        qs.y = h2u(__floats2half2_rn(qv.z, qv.w));
        ks.x = h2u(__floats2half2_rn(kv.x, kv.y));
        ks.y = h2u(__floats2half2_rn(kv.z, kv.w));
        vs.x = h2u(__floats2half2_rn(vv.x, vv.y));
        vs.y = h2u(__floats2half2_rn(vv.z, vv.w));
        *(uint2*)(smu + QHP_U + base) = qs;
        *(uint2*)(smu + KHP_U + base) = ks;
        *(uint2*)(smu + VHP_U + base) = vs;
    }
    __syncthreads();

    // ldmatrix per-lane base addresses (bytes)
    const uint32_t smb = smem_u32(smu);
    const uint32_t qrow  = 16 * wid + (lane & 7) + 8 * ((lane >> 3) & 1);
    const uint32_t qaddr = smb + 4 * (QHP_U + qrow * 20 + 4 * ((lane >> 4) & 1));
    const uint32_t krow  = (lane & 7) + 8 * ((lane >> 4) & 1);
    const uint32_t kaddr = smb + 4 * (KHP_U + krow * 20 + 4 * ((lane >> 3) & 1));
    const uint32_t vrow  = (lane & 7) + 8 * ((lane >> 3) & 1);
    const uint32_t vaddr = smb + 4 * (VHP_U + vrow * 20 + 4 * ((lane >> 4) & 1));

    const int arow = 16 * wid + (lane >> 2);
    const int jl   = lane & 3;
    const int r1 = arow;
    const int r2 = arow + 8;

    // ---- init accumulators with RPE bias: bias = bs2*sin((col-row)*pi/127)
    // per-row sin/cos from the SCT table (r1,r2 in [0,128))
    const float bs2 = 0.2f * __sinf((float)h * (3.14159265358979323846f / 128.0f));
    const float f1s = bs2 * smf[SCT_U + 2 * r1];
    const float f1c = bs2 * smf[SCT_U + 2 * r1 + 1];
    const float f2s = bs2 * smf[SCT_U + 2 * r2];
    const float f2c = bs2 * smf[SCT_U + 2 * r2 + 1];

    float c[16][4];
    #pragma unroll
    for (int nt = 0; nt < 16; ++nt) {
        const int col0 = 8 * nt + 2 * jl;
        float4 t = *(const float4*)(smf + SCT_U + 2 * col0);   // {s0,c0,s1,c1}
        c[nt][0] = t.x * f1c - t.y * f1s;
        c[nt][1] = t.z * f1c - t.w * f1s;
        c[nt][2] = t.x * f2c - t.y * f2s;
        c[nt][3] = t.z * f2c - t.w * f2s;
    }

    // ---- QK^T: warp wid -> rows 16*wid..16*wid+15, 2 chunks of k16 ----
    #pragma unroll
    for (int ch = 0; ch < 2; ++ch) {
        uint32_t qh0, qh1, qh2, qh3;
        LDSM_X4(qh0, qh1, qh2, qh3, qaddr + ch * 32);
        #pragma unroll
        for (int t = 0; t < 8; ++t) {
            uint32_t k00, k01, k10, k11;
            LDSM_X4(k00, k01, k10, k11, kaddr + t * 1280 + ch * 32);  // 16 rows * 80B
            MMA_F16(c[2*t][0], c[2*t][1], c[2*t][2], c[2*t][3],
                    qh0, qh1, qh2, qh3, k00, k01);
            MMA_F16(c[2*t+1][0], c[2*t+1][1], c[2*t+1][2], c[2*t+1][3],
                    qh0, qh1, qh2, qh3, k10, k11);
        }
    }

    // ---- epilogue: |.| sums + row sumsq (bias already inside c) ----
    float sq1 = 0.0f, sq2 = 0.0f, s_abs = 0.0f;
    #pragma unroll
    for (int nt = 0; nt < 16; ++nt) {
        sq1 += c[nt][0] * c[nt][0] + c[nt][1] * c[nt][1];
        sq2 += c[nt][2] * c[nt][2] + c[nt][3] * c[nt][3];
        s_abs += fabsf(c[nt][0]) + fabsf(c[nt][1]) + fabsf(c[nt][2]) + fabsf(c[nt][3]);
    }
    sq1 += __shfl_xor_sync(0xffffffffu, sq1, 1);
    sq1 += __shfl_xor_sync(0xffffffffu, sq1, 2);
    sq2 += __shfl_xor_sync(0xffffffffu, sq2, 1);
    sq2 += __shfl_xor_sync(0xffffffffu, sq2, 2);
    #pragma unroll
    for (int m = 16; m; m >>= 1)
        s_abs += __shfl_xor_sync(0xffffffffu, s_abs, m);
    if (lane == 0) atomicAdd(&g_wsum[wi], s_abs);   // per-warp, no smem/barrier

    // ---- transform: pack 1-cos(v*(pi/2)/norm) straight to half2 A-frags ----
    uint32_t aw[16][2];
    {
        const float inv1 = 1.57079632679489662f * rsqrtf(fmaxf(sq1, 1e-24f));
        const float inv2 = 1.57079632679489662f * rsqrtf(fmaxf(sq2, 1e-24f));
        #pragma unroll
        for (int nt = 0; nt < 16; ++nt) {
            float t0 = 1.0f - __cosf(c[nt][0] * inv1);
            float t1 = 1.0f - __cosf(c[nt][1] * inv1);
            float t2 = 1.0f - __cosf(c[nt][2] * inv2);
            float t3 = 1.0f - __cosf(c[nt][3] * inv2);
            aw[nt][0] = h2u(__floats2half2_rn(t0, t1));
            aw[nt][1] = h2u(__floats2half2_rn(t2, t3));
        }
    }

    // ---- AV: A-frags from aw, V B-frags via ldmatrix.trans ----
    float oacc[4][4];
    #pragma unroll
    for (int nt = 0; nt < 4; ++nt)
        #pragma unroll
        for (int j = 0; j < 4; ++j) oacc[nt][j] = 0.0f;

    #pragma unroll
    for (int ch = 0; ch < 8; ++ch) {
        const uint32_t ah0 = aw[2 * ch][0];
        const uint32_t ah1 = aw[2 * ch][1];
        const uint32_t ah2 = aw[2 * ch + 1][0];
        const uint32_t ah3 = aw[2 * ch + 1][1];

        uint32_t v00, v01, v02, v03, v10, v11, v12, v13;
        LDSM_X4T(v00, v01, v02, v03, vaddr + ch * 1280);        // d 0-15
        LDSM_X4T(v10, v11, v12, v13, vaddr + ch * 1280 + 32);   // d 16-31
        MMA_F16(oacc[0][0], oacc[0][1], oacc[0][2], oacc[0][3],
                ah0, ah1, ah2, ah3, v00, v01);
        MMA_F16(oacc[1][0], oacc[1][1], oacc[1][2], oacc[1][3],
                ah0, ah1, ah2, ah3, v02, v03);
        MMA_F16(oacc[2][0], oacc[2][1], oacc[2][2], oacc[2][3],
                ah0, ah1, ah2, ah3, v10, v11);
        MMA_F16(oacc[3][0], oacc[3][1], oacc[3][2], oacc[3][3],
                ah0, ah1, ah2, ah3, v12, v13);
    }

    // ---- store y (ungated) as fp16 with streaming hint ----
    const size_t obase = ((size_t)(b * HW_) + (size_t)h * W_) * C_ + n * HD_;
    const int ocol = 2 * jl;
    #pragma unroll
    for (int nt = 0; nt < 4; ++nt) {
        uint32_t p1 = h2u(__floats2half2_rn(oacc[nt][0], oacc[nt][1]));
        uint32_t p2 = h2u(__floats2half2_rn(oacc[nt][2], oacc[nt][3]));
        STG32_CS(g_yh + obase + (size_t)r1 * C_ + 8 * nt + ocol, p1);
        STG32_CS(g_yh + obase + (size_t)r2 * C_ + 8 * nt + ocol, p2);
    }
}

// ---------------------------------------------------------------------------
// Gate: mean |attn| per window, global max, M = max(mean/max, 0.5).
// Resets g_wsum for the next graph replay.
// ---------------------------------------------------------------------------
__global__ void gate_kernel() {
    __shared__ float red[512];
    const int t = threadIdx.x;
    float mean = g_wsum[t] * (1.0f / 131072.0f);   // / (NH*W*W)
    g_wsum[t] = 0.0f;
    red[t] = mean;
    __syncthreads();
    for (int s = 256; s > 0; s >>= 1) {
        if (t < s) red[t] = fmaxf(red[t], red[t + s]);
        __syncthreads();
    }
    g_M[t] = fmaxf(mean / red[0], 0.5f);
}

// ---------------------------------------------------------------------------
// Blend: out = M * y + (1 - M) * res   (pure bandwidth, streaming hints)
// ---------------------------------------------------------------------------
__global__ __launch_bounds__(256) void blend_kernel(const float* __restrict__ resx,
                                                    float* __restrict__ out) {
    const int i  = blockIdx.x * 256 + threadIdx.x;   // float4 index
    const int wi = i >> 13;                          // / (W_*C_/4 = 8192)
    const float Mw   = g_M[wi];
    const float oneM = 1.0f - Mw;
    uint2 yr;
    asm volatile("ld.global.cs.v2.b32 {%0,%1}, [%2];"
                 : "=r"(yr.x), "=r"(yr.y)
                 : "l"((const __half2*)g_yh + 2 * (size_t)i));
    float2 y01 = __half22float2(*(__half2*)&yr.x);
    float2 y23 = __half22float2(*(__half2*)&yr.y);
    float4 r;
    asm volatile("ld.global.cs.v4.f32 {%0,%1,%2,%3}, [%4];"
                 : "=f"(r.x), "=f"(r.y), "=f"(r.z), "=f"(r.w)
                 : "l"(resx + 4 * (size_t)i));
    float4 o;
    o.x = fmaf(Mw, y01.x, oneM * r.x);
    o.y = fmaf(Mw, y01.y, oneM * r.y);
    o.z = fmaf(Mw, y23.x, oneM * r.z);
    o.w = fmaf(Mw, y23.y, oneM * r.w);
    asm volatile("st.global.cs.v4.f32 [%0], {%1,%2,%3,%4};"
                 :: "l"(out + 4 * (size_t)i),
                    "f"(o.x), "f"(o.y), "f"(o.z), "f"(o.w) : "memory");
}

// ---------------------------------------------------------------------------
extern "C" void kernel_launch(void* const* d_in, const int* in_sizes, int n_in,
                              void* d_out, int out_size) {
    (void)in_sizes; (void)n_in; (void)out_size;
    const float* qkv  = (const float*)d_in[0];
    const float* resx = (const float*)d_in[1];
    float* out = (float*)d_out;

    cudaFuncSetAttribute(fused_kernel, cudaFuncAttributeMaxDynamicSharedMemorySize,
                         FUSED_SMEM);

    fused_kernel<<<NCTA, 256, FUSED_SMEM>>>(qkv);
    gate_kernel<<<1, NWIN>>>();
    blend_kernel<<<(B_ * HW_ * C_ / 4) / 256, 256>>>(resx, out);
}